// round 3
// baseline (speedup 1.0000x reference)
#include <cuda_runtime.h>
#include <math.h>

namespace {
constexpr int B_ = 32, L_ = 32, D_ = 512, H_ = 512;
constexpr int H2_ = 1024, H5_ = 2560;
constexpr int PSLOT = 64, ZSLOT = 63;   // pool slots per batch; 63 = zero slot
constexpr int CSLOT = 96, DSLOT = 95;   // cache slots per batch; 95 = dummy
constexpr int NCTA = 148;               // persistent grid (<= SM count, all resident)
}

__device__ float g_poolH[B_ * PSLOT * H_];
__device__ float g_poolC[B_ * PSLOT * H_];
__device__ float g_uL[B_ * PSLOT * H5_];   // uL[s] = h_s @ Wc[0:512,:]
__device__ float g_uR[B_ * PSLOT * H5_];   // uR[s] = h_s @ Wc[512:1024,:]
__device__ float g_cacheH[B_ * CSLOT * H_];
__device__ float g_cacheC[B_ * CSLOT * H_];
__device__ float g_logit[B_ * CSLOT];
__device__ int4  g_tasks[2 * B_];          // x=batch, y=lslot, z=rslot, w=cache slot
__device__ int   g_newSlot[B_];            // slot needing u next step (ZSLOT if frozen)
__device__ int   g_slotOf[B_ * L_];        // position -> pool slot
__device__ int   g_cidx[B_ * L_];          // pair -> cache slot
__device__ unsigned g_barCnt[80];          // per-instance grid-barrier counters

__device__ __forceinline__ float sigm(float x) { return 1.f / (1.f + expf(-x)); }

__device__ __forceinline__ void gridBar(int id) {
    __syncthreads();
    if (threadIdx.x == 0) {
        __threadfence();
        atomicAdd(&g_barCnt[id], 1u);
        while (*(volatile unsigned*)&g_barCnt[id] < (unsigned)NCTA) {}
        __threadfence();
    }
    __syncthreads();
}

// ---------------------------------------------------------------------------
__global__ void kInit() {
    int t = blockIdx.x * blockDim.x + threadIdx.x;   // 4096 threads
    if (t < 80) g_barCnt[t] = 0u;
    if (t < B_ * L_) {
        int p = t % L_;
        g_slotOf[t] = p;
        g_cidx[t]   = (p < L_ - 1) ? p : DSLOT;
    }
    if (t < B_) g_logit[t * CSLOT + DSLOT] = 0.f;
    for (int i = t; i < B_ * H_; i += 4096) {
        int b = i / H_, j = i % H_;
        g_poolH[(b * PSLOT + ZSLOT) * H_ + j] = 0.f;
        g_poolC[(b * PSLOT + ZSLOT) * H_ + j] = 0.f;
        g_cacheH[(b * CSLOT + DSLOT) * H_ + j] = 0.f;
        g_cacheC[(b * CSLOT + DSLOT) * H_ + j] = 0.f;
    }
    for (int i = t; i < B_ * H5_; i += 4096) {
        int b = i / H5_, j = i % H5_;
        g_uL[(b * PSLOT + ZSLOT) * H5_ + j] = 0.f;
        g_uR[(b * PSLOT + ZSLOT) * H5_ + j] = 0.f;
    }
}

// ---------------------------------------------------------------------------
// Leaf GEMM: hc = inp @ W_word + b_word. M=1024, N=1024, K=512.
// ---------------------------------------------------------------------------
__global__ void __launch_bounds__(256) kLeafGemm(const float* __restrict__ inp,
                                                 const float* __restrict__ Ww,
                                                 const float* __restrict__ bw,
                                                 float* __restrict__ nodes) {
    const int m0 = blockIdx.x * 64, n0 = blockIdx.y * 64;
    __shared__ __align__(16) float Xs[16][68];
    __shared__ __align__(16) float Ws[16][68];
    const int ty = threadIdx.x / 16, tx = threadIdx.x % 16;
    const int lm = threadIdx.x / 4,  lq = threadIdx.x % 4;
    const int wr = threadIdx.x / 16, wc = threadIdx.x % 16;
    float acc[4][4] = {};
    for (int k0 = 0; k0 < D_; k0 += 16) {
        float4 xv = *(const float4*)&inp[(m0 + lm) * D_ + k0 + lq * 4];
        Xs[lq*4+0][lm]=xv.x; Xs[lq*4+1][lm]=xv.y; Xs[lq*4+2][lm]=xv.z; Xs[lq*4+3][lm]=xv.w;
        *(float4*)&Ws[wr][wc*4] = *(const float4*)&Ww[(k0 + wr) * H2_ + n0 + wc * 4];
        __syncthreads();
#pragma unroll
        for (int kk = 0; kk < 16; kk++) {
            float4 a = *(const float4*)&Xs[kk][ty*4];
            float4 w = *(const float4*)&Ws[kk][tx*4];
            acc[0][0]+=a.x*w.x; acc[0][1]+=a.x*w.y; acc[0][2]+=a.x*w.z; acc[0][3]+=a.x*w.w;
            acc[1][0]+=a.y*w.x; acc[1][1]+=a.y*w.y; acc[1][2]+=a.y*w.z; acc[1][3]+=a.y*w.w;
            acc[2][0]+=a.z*w.x; acc[2][1]+=a.z*w.y; acc[2][2]+=a.z*w.z; acc[2][3]+=a.z*w.w;
            acc[3][0]+=a.w*w.x; acc[3][1]+=a.w*w.y; acc[3][2]+=a.w*w.z; acc[3][3]+=a.w*w.w;
        }
        __syncthreads();
    }
#pragma unroll
    for (int e = 0; e < 4; e++) {
        int m = m0 + ty * 4 + e, b = m / L_, l = m % L_;
#pragma unroll
        for (int f = 0; f < 4; f++) {
            int n = n0 + tx * 4 + f;
            float v = acc[e][f] + bw[n];
            if (n < H_) {
                g_poolH[(b * PSLOT + l) * H_ + n] = v;
                nodes[(b * 63 + l) * H_ + n] = v;
            } else {
                g_poolC[(b * PSLOT + l) * H_ + (n - H_)] = v;
            }
        }
    }
}

// ---------------------------------------------------------------------------
// u-GEMM for all leaves: M=1024 (b,slot), N=5120 (uL|uR), K=512.
// ---------------------------------------------------------------------------
__global__ void __launch_bounds__(256) kUGemm0(const float* __restrict__ Wc) {
    const int m0 = blockIdx.x * 64, n0 = blockIdx.y * 64;
    const int half = (n0 >= H5_) ? 1 : 0;
    const int nn = n0 - half * H5_;
    __shared__ __align__(16) float Xs[16][68];
    __shared__ __align__(16) float Ws[16][68];
    const int ty = threadIdx.x / 16, tx = threadIdx.x % 16;
    const int lm = threadIdx.x / 4,  lq = threadIdx.x % 4;
    const int wr = threadIdx.x / 16, wc = threadIdx.x % 16;
    float acc[4][4] = {};
    for (int k0 = 0; k0 < H_; k0 += 16) {
        int m = m0 + lm;
        const float* src = &g_poolH[(((m >> 5) * PSLOT) + (m & 31)) * H_];
        float4 xv = *(const float4*)&src[k0 + lq * 4];
        Xs[lq*4+0][lm]=xv.x; Xs[lq*4+1][lm]=xv.y; Xs[lq*4+2][lm]=xv.z; Xs[lq*4+3][lm]=xv.w;
        *(float4*)&Ws[wr][wc*4] = *(const float4*)&Wc[(half * H_ + k0 + wr) * H5_ + nn + wc * 4];
        __syncthreads();
#pragma unroll
        for (int kk = 0; kk < 16; kk++) {
            float4 a = *(const float4*)&Xs[kk][ty*4];
            float4 w = *(const float4*)&Ws[kk][tx*4];
            acc[0][0]+=a.x*w.x; acc[0][1]+=a.x*w.y; acc[0][2]+=a.x*w.z; acc[0][3]+=a.x*w.w;
            acc[1][0]+=a.y*w.x; acc[1][1]+=a.y*w.y; acc[1][2]+=a.y*w.z; acc[1][3]+=a.y*w.w;
            acc[2][0]+=a.z*w.x; acc[2][1]+=a.z*w.y; acc[2][2]+=a.z*w.z; acc[2][3]+=a.z*w.w;
            acc[3][0]+=a.w*w.x; acc[3][1]+=a.w*w.y; acc[3][2]+=a.w*w.z; acc[3][3]+=a.w*w.w;
        }
        __syncthreads();
    }
    float* U = half ? g_uR : g_uL;
#pragma unroll
    for (int e = 0; e < 4; e++) {
        int m = m0 + ty * 4 + e;
        float* dst = &U[(((m >> 5) * PSLOT) + (m & 31)) * H5_ + nn];
        *(float4*)&dst[tx * 4] = make_float4(acc[e][0], acc[e][1], acc[e][2], acc[e][3]);
    }
}

// ---------------------------------------------------------------------------
// Pair activation from cached u halves. Caller guarantees uniform control.
// lt in [0,nthr), nthr multiple of 32; red has nw = nthr/32 slots.
// ---------------------------------------------------------------------------
__device__ __forceinline__ void actPair(int b, int ls, int rs, int cs,
                                        const float* __restrict__ bc,
                                        const float* __restrict__ q,
                                        int lt, int nthr, float* red, int nw) {
    const float* ul = &g_uL[(b * PSLOT + ls) * H5_];
    const float* ur = &g_uR[(b * PSLOT + rs) * H5_];
    const float* cl = &g_poolC[(b * PSLOT + ls) * H_];
    const float* cr = &g_poolC[(b * PSLOT + rs) * H_];
    float* oh = &g_cacheH[(b * CSLOT + cs) * H_];
    float* oc = &g_cacheC[(b * CSLOT + cs) * H_];
    float acc = 0.f;
    for (int j = lt; j < H_; j += nthr) {
        float g0 = ul[j]        + ur[j]        + bc[j];
        float g1 = ul[H_ + j]   + ur[H_ + j]   + bc[H_ + j];
        float g2 = ul[2*H_ + j] + ur[2*H_ + j] + bc[2*H_ + j];
        float g3 = ul[3*H_ + j] + ur[3*H_ + j] + bc[3*H_ + j];
        float g4 = ul[4*H_ + j] + ur[4*H_ + j] + bc[4*H_ + j];
        float c = cl[j] * sigm(g1 + 1.f) + cr[j] * sigm(g2 + 1.f)
                + tanhf(g3) * sigm(g0);
        float h = sigm(g4) * tanhf(c);
        oh[j] = h; oc[j] = c; acc += h * q[j];
    }
    for (int o = 16; o > 0; o >>= 1) acc += __shfl_down_sync(0xffffffffu, acc, o);
    if ((lt & 31) == 0) red[lt >> 5] = acc;
    __syncthreads();
    if (lt == 0) {
        float s = 0.f;
        for (int w = 0; w < nw; w++) s += red[w];
        g_logit[b * CSLOT + cs] = s;
    }
}

// Step-0 activation: all adjacent leaf pairs.
__global__ void __launch_bounds__(128) kAct0(const int* __restrict__ len,
                                             const float* __restrict__ bc,
                                             const float* __restrict__ q) {
    __shared__ float red[4];
    int b = blockIdx.y, j = blockIdx.x;
    if (j < len[b] - 1)
        actPair(b, j, j + 1, j, bc, q, threadIdx.x, 128, red, 4);
}

// ---------------------------------------------------------------------------
// Select for batch b at step stepI (all threads of CTA participate).
// ---------------------------------------------------------------------------
__device__ void doSelect(int b, int stepI, const int* __restrict__ len,
                         float* __restrict__ nodes, float* __restrict__ hf,
                         float* __restrict__ cf,
                         int* sPos, int* sPair, int* sKp) {
    int t = threadIdx.x;
    if (t < 32) sPos[t] = g_slotOf[b * L_ + t];
    if (t < 31) sPair[t] = g_cidx[b * L_ + t];
    __syncthreads();
    int lb = len[b];
    if (stepI < lb - 1) {
        if (t == 0) {
            int cand = lb - 1 - stepI, k = 0;
            float best = -1e30f;
            for (int j = 0; j < cand; j++) {
                float v = g_logit[b * CSLOT + sPair[j]];
                if (v > best) { best = v; k = j; }
            }
            *sKp = k;
        }
        __syncthreads();
        int k = *sKp, cs = sPair[k], mslot = 32 + stepI;
        const float* ch = &g_cacheH[(b * CSLOT + cs) * H_];
        const float* cc = &g_cacheC[(b * CSLOT + cs) * H_];
        float* ph = &g_poolH[(b * PSLOT + mslot) * H_];
        float* pc = &g_poolC[(b * PSLOT + mslot) * H_];
        float* nd = &nodes[(b * 63 + 32 + stepI) * H_];
        for (int j = t; j < H_; j += blockDim.x) {
            float hv = ch[j], cv = cc[j];
            ph[j] = hv; pc[j] = cv; nd[j] = hv;
            if (stepI == L_ - 2) { hf[b * H_ + j] = hv; cf[b * H_ + j] = cv; }
        }
        if (t < 32) {
            int np = (t < k) ? sPos[t] : (t == k) ? mslot : (t < 31) ? sPos[t + 1] : ZSLOT;
            g_slotOf[b * L_ + t] = np;
        }
        if (t < 31) {
            int np;
            if      (t <  k - 1) np = sPair[t];
            else if (t == k - 1) np = 31 + 2 * stepI;
            else if (t == k)     np = 32 + 2 * stepI;
            else if (t < 30)     np = sPair[t + 1];
            else                 np = DSLOT;
            g_cidx[b * L_ + t] = np;
        }
        if (t == 0) {
            int A = 31 + 2 * stepI, Bc = 32 + 2 * stepI;
            g_tasks[2 * b] = (k > 0) ? make_int4(b, sPos[k - 1], mslot, A)
                                     : make_int4(b, ZSLOT, ZSLOT, DSLOT);
            int r = (k + 2 <= 31) ? sPos[k + 2] : ZSLOT;
            g_tasks[2 * b + 1] = make_int4(b, mslot, r, Bc);
            g_newSlot[b] = mslot;
        }
    } else {
        float* nd = &nodes[(b * 63 + 32 + stepI) * H_];
        if (stepI == L_ - 2) {
            int rs = sPos[0];
            const float* ph = &g_poolH[(b * PSLOT + rs) * H_];
            const float* pc = &g_poolC[(b * PSLOT + rs) * H_];
            for (int j = t; j < H_; j += blockDim.x) {
                float hv = ph[j];
                nd[j] = hv; hf[b * H_ + j] = hv; cf[b * H_ + j] = pc[j];
            }
        } else {
            int cs = sPair[0];
            const float* ch = &g_cacheH[(b * CSLOT + cs) * H_];
            for (int j = t; j < H_; j += blockDim.x) nd[j] = ch[j];
        }
        if (t == 0) {
            g_tasks[2 * b]     = make_int4(b, ZSLOT, ZSLOT, DSLOT);
            g_tasks[2 * b + 1] = make_int4(b, ZSLOT, ZSLOT, DSLOT);
            g_newSlot[b] = ZSLOT;
        }
    }
    __syncthreads();
}

// ---------------------------------------------------------------------------
// Persistent kernel: select_0 then 30 steps of [uGEMM | act+select].
// ---------------------------------------------------------------------------
__global__ void __launch_bounds__(256, 1) kPersist(const int* __restrict__ len,
                                                   const float* __restrict__ Wc,
                                                   const float* __restrict__ bc,
                                                   const float* __restrict__ q,
                                                   float* __restrict__ nodes,
                                                   float* __restrict__ hf,
                                                   float* __restrict__ cf) {
    const int cta = blockIdx.x, tid = threadIdx.x;
    __shared__ __align__(16) float As[16][33];
    __shared__ __align__(16) float Bs[16][68];
    __shared__ int sSlot[32];
    __shared__ int sPos[32], sPair[31], sK;
    __shared__ float red[8];

    if (cta < B_) doSelect(cta, 0, len, nodes, hf, cf, sPos, sPair, &sK);
    gridBar(0);

    for (int i = 1; i <= L_ - 2; i++) {
        // ---- phase 1: u-GEMM for new nodes (M=32, N=5120, K=512; 80 tiles)
        if (tid < B_) sSlot[tid] = ((volatile int*)g_newSlot)[tid];
        __syncthreads();
        if (cta < 80) {
            const int n0 = cta * 64;
            const int half = (n0 >= H5_) ? 1 : 0;
            const int nn = n0 - half * H5_;
            const int mg = tid >> 4, ng = tid & 15;
            const int wr = tid >> 4, wc = tid & 15;
            const int mA = tid & 31, kA = tid >> 5;
            const int mA2 = (tid + 256) & 31, kA2 = (tid + 256) >> 5;
            float acc[2][4] = {};
            // register-prefetch pipeline
            float a0r = g_poolH[(mA * PSLOT + sSlot[mA]) * H_ + kA];
            float a1r = g_poolH[(mA2 * PSLOT + sSlot[mA2]) * H_ + kA2];
            float4 b4r = *(const float4*)&Wc[(half * H_ + wr) * H5_ + nn + wc * 4];
            for (int k0 = 0; k0 < H_; k0 += 16) {
                As[kA][mA] = a0r;
                As[kA2][mA2] = a1r;
                *(float4*)&Bs[wr][wc * 4] = b4r;
                __syncthreads();
                if (k0 + 16 < H_) {
                    a0r = g_poolH[(mA * PSLOT + sSlot[mA]) * H_ + k0 + 16 + kA];
                    a1r = g_poolH[(mA2 * PSLOT + sSlot[mA2]) * H_ + k0 + 16 + kA2];
                    b4r = *(const float4*)&Wc[(half * H_ + k0 + 16 + wr) * H5_ + nn + wc * 4];
                }
#pragma unroll
                for (int kk = 0; kk < 16; kk++) {
                    float av0 = As[kk][mg * 2], av1 = As[kk][mg * 2 + 1];
                    float4 bv = *(const float4*)&Bs[kk][ng * 4];
                    acc[0][0]+=av0*bv.x; acc[0][1]+=av0*bv.y; acc[0][2]+=av0*bv.z; acc[0][3]+=av0*bv.w;
                    acc[1][0]+=av1*bv.x; acc[1][1]+=av1*bv.y; acc[1][2]+=av1*bv.z; acc[1][3]+=av1*bv.w;
                }
                __syncthreads();
            }
            float* U = half ? g_uR : g_uL;
#pragma unroll
            for (int e = 0; e < 2; e++) {
                int m = mg * 2 + e;
                *(float4*)&U[(m * PSLOT + sSlot[m]) * H5_ + nn + ng * 4] =
                    make_float4(acc[e][0], acc[e][1], acc[e][2], acc[e][3]);
            }
        }
        gridBar(2 * i - 1);
        // ---- phase 2: activation (2 tasks in warp-halves) + select
        if (cta < B_) {
            int4 tk = (tid < 128) ? g_tasks[2 * cta] : g_tasks[2 * cta + 1];
            actPair(cta, tk.y, tk.z, tk.w, bc, q, tid & 127, 128,
                    red + ((tid >> 7) << 2), 4);
            __syncthreads();
            doSelect(cta, i, len, nodes, hf, cf, sPos, sPair, &sK);
        }
        gridBar(2 * i);
    }
}

// ---------------------------------------------------------------------------
extern "C" void kernel_launch(void* const* d_in, const int* in_sizes, int n_in,
                              void* d_out, int out_size) {
    const float* inp = (const float*)d_in[0];
    const int*   len = (const int*)  d_in[1];
    const float* Ww  = (const float*)d_in[2];
    const float* bw  = (const float*)d_in[3];
    const float* Wc  = (const float*)d_in[4];
    const float* bc  = (const float*)d_in[5];
    const float* q   = (const float*)d_in[6];
    float* out   = (float*)d_out;
    float* hf    = out;
    float* cf    = out + B_ * H_;
    float* nodes = out + 2 * B_ * H_;

    kInit<<<16, 256>>>();
    kLeafGemm<<<dim3(16, 16), 256>>>(inp, Ww, bw, nodes);
    kUGemm0<<<dim3(16, 80), 256>>>(Wc);
    kAct0<<<dim3(31, B_), 128>>>(len, bc, q);
    kPersist<<<NCTA, 256>>>(len, Wc, bc, q, nodes, hf, cf);
}